// round 13
// baseline (speedup 1.0000x reference)
#include <cuda_runtime.h>
#include <cstdint>

// ---------------------------------------------------------------------------
// GATv2 forward, CSR + fused softmax/aggregate/pool.
//   gemm: 3xTF32 mma.sync.m16n8k8, W PRE-SPLIT once into tf32 hi/lo device
//         planes (R12 re-split W per block: ~70K extra instrs/block, alu=21%).
//         B staged to smem via uint4 copies (conflict-free STS.128); A frags
//         loaded directly from gmem (L1-cached, 2x reuse); warp = 2m x 4n.
//   aggregate: BLOCK per dst node (measured best).
//   CSR build: hist -> 3-step multiblock scan -> fill.
// Shapes: N=50000, E=800000, D=128, H=4, C=32, HC=128, G=64.
// edge_index / batch_ids arrive as int32 (harness canonicalizes int64).
// ---------------------------------------------------------------------------

#define NMAX   50048
#define EMAX   800000
#define GMAX   256
#define BP     136   // smem B pitch: fragment bank = 8*tig + g + 8j (bijective)

__device__ float    g_xl[(size_t)NMAX * 128];
__device__ float    g_xr[(size_t)NMAX * 128];
__device__ uint32_t g_wh[2 * 128 * 128];
__device__ uint32_t g_wlo[2 * 128 * 128];
__device__ int      g_cnt[NMAX];
__device__ int      g_rowptr[NMAX + 1];
__device__ int      g_cursor[NMAX];
__device__ int      g_csrc[EMAX];
__device__ int      g_bsum[64];
__device__ int      g_boff[64];
__device__ float    g_pooled[GMAX * 128];

__device__ __forceinline__ int clampi(int v, int lo, int hi) {
    return v < lo ? lo : (v > hi ? hi : v);
}

__device__ __forceinline__ uint32_t f2tf(float f) {
    uint32_t r;
    asm("cvt.rna.tf32.f32 %0, %1;" : "=r"(r) : "f"(f));
    return r;
}

__device__ __forceinline__ void mma_tf32(float* c, const uint32_t* a,
                                         uint32_t b0, uint32_t b1) {
    asm volatile(
        "mma.sync.aligned.m16n8k8.row.col.f32.tf32.tf32.f32 "
        "{%0,%1,%2,%3}, {%4,%5,%6,%7}, {%8,%9}, {%0,%1,%2,%3};"
        : "+f"(c[0]), "+f"(c[1]), "+f"(c[2]), "+f"(c[3])
        : "r"(a[0]), "r"(a[1]), "r"(a[2]), "r"(a[3]), "r"(b0), "r"(b1));
}

// ---------------------------------------------------------------------------
__global__ void init_kernel(int n_nodes, int n_pool) {
    int i = blockIdx.x * blockDim.x + threadIdx.x;
    int stride = gridDim.x * blockDim.x;
    for (int idx = i; idx < n_nodes; idx += stride) g_cnt[idx] = 0;
    for (int idx = i; idx < n_pool; idx += stride) g_pooled[idx] = 0.f;
}

// ---------------------------------------------------------------------------
// One-time W split: g_wh/g_wlo[cb*16384 + k*128 + col], tf32 hi + residual lo.
// ---------------------------------------------------------------------------
__global__ void presplit_kernel(const float* __restrict__ Wl,
                                const float* __restrict__ Wr) {
    int i = blockIdx.x * 256 + threadIdx.x;
    if (i >= 2 * 16384) return;
    float v = (i < 16384) ? Wl[i] : Wr[i - 16384];
    uint32_t h = f2tf(v);
    g_wh[i]  = h;
    g_wlo[i] = f2tf(v - __uint_as_float(h));
}

// ---------------------------------------------------------------------------
__global__ void hist_kernel(const int* __restrict__ ei, int E, int N) {
    int i = blockIdx.x * blockDim.x + threadIdx.x;
    int stride = gridDim.x * blockDim.x;
    for (int e = i; e < E; e += stride)
        atomicAdd(&g_cnt[clampi(ei[E + e], 0, N - 1)], 1);
}

// ---------------------------------------------------------------------------
// 3xTF32 GEMM. Block: 64 rows x 128 cols. 8 warps: wmh=w&1 (32-row half),
// wn=w>>1 (32-col group). Warp tile: 2 m-tiles (16) x 4 n-tiles (8).
// B chunks of 32 k staged to smem from presplit planes; A frags from gmem.
// ---------------------------------------------------------------------------
__global__ void __launch_bounds__(256) gemm_kernel(
    const float* __restrict__ x, int N)
{
    __shared__ uint32_t Bh[32 * BP];   // 17.4 KB
    __shared__ uint32_t Bl[32 * BP];   // 17.4 KB

    int cb   = blockIdx.x;
    int row0 = blockIdx.y * 64;
    const uint32_t* wh = g_wh  + cb * 16384;
    const uint32_t* wl = g_wlo + cb * 16384;
    float* dst = cb ? g_xr : g_xl;

    int t = threadIdx.x;
    int w = t >> 5, lane = t & 31;
    int wmh = w & 1, wn = w >> 1;
    int g = lane >> 2, tig = lane & 3;

    // precomputed clamped A rows for this warp's fragments
    int ra0 = clampi(row0 + wmh * 32 + g, 0, N - 1);          // mt=0 rows g
    int ra1 = clampi(row0 + wmh * 32 + g + 8, 0, N - 1);      // mt=0 rows g+8
    int rb0 = clampi(row0 + wmh * 32 + 16 + g, 0, N - 1);     // mt=1
    int rb1 = clampi(row0 + wmh * 32 + 16 + g + 8, 0, N - 1);

    float c[8][4];
#pragma unroll
    for (int j = 0; j < 8; j++)
#pragma unroll
        for (int i = 0; i < 4; i++) c[j][i] = 0.f;

#pragma unroll
    for (int k0 = 0; k0 < 128; k0 += 32) {
        // stage B hi/lo: pure uint4 copies (no cvt — presplit)
#pragma unroll
        for (int i = 0; i < 4; i++) {
            int idx = t + i * 256;            // 0..1023 over 32k x 32 uint4
            int k = idx >> 5, j4 = idx & 31;
            *(uint4*)&Bh[k * BP + j4 * 4] = *(const uint4*)&wh[(k0 + k) * 128 + j4 * 4];
            *(uint4*)&Bl[k * BP + j4 * 4] = *(const uint4*)&wl[(k0 + k) * 128 + j4 * 4];
        }
        __syncthreads();

#pragma unroll
        for (int ks = 0; ks < 32; ks += 8) {
            int kk = k0 + ks;
            // A fragments straight from gmem (+ on-the-fly hi/lo split)
            uint32_t ah[2][4], al[2][4];
            {
                float f0 = x[(size_t)ra0 * 128 + kk + tig];
                float f1 = x[(size_t)ra1 * 128 + kk + tig];
                float f2 = x[(size_t)ra0 * 128 + kk + tig + 4];
                float f3 = x[(size_t)ra1 * 128 + kk + tig + 4];
                ah[0][0] = f2tf(f0); al[0][0] = f2tf(f0 - __uint_as_float(ah[0][0]));
                ah[0][1] = f2tf(f1); al[0][1] = f2tf(f1 - __uint_as_float(ah[0][1]));
                ah[0][2] = f2tf(f2); al[0][2] = f2tf(f2 - __uint_as_float(ah[0][2]));
                ah[0][3] = f2tf(f3); al[0][3] = f2tf(f3 - __uint_as_float(ah[0][3]));
                f0 = x[(size_t)rb0 * 128 + kk + tig];
                f1 = x[(size_t)rb1 * 128 + kk + tig];
                f2 = x[(size_t)rb0 * 128 + kk + tig + 4];
                f3 = x[(size_t)rb1 * 128 + kk + tig + 4];
                ah[1][0] = f2tf(f0); al[1][0] = f2tf(f0 - __uint_as_float(ah[1][0]));
                ah[1][1] = f2tf(f1); al[1][1] = f2tf(f1 - __uint_as_float(ah[1][1]));
                ah[1][2] = f2tf(f2); al[1][2] = f2tf(f2 - __uint_as_float(ah[1][2]));
                ah[1][3] = f2tf(f3); al[1][3] = f2tf(f3 - __uint_as_float(ah[1][3]));
            }

#pragma unroll
            for (int j = 0; j < 4; j++) {
                int colw = wn * 32 + j * 8 + g;
                uint32_t bh0 = Bh[(ks + tig)     * BP + colw];
                uint32_t bh1 = Bh[(ks + tig + 4) * BP + colw];
                uint32_t bl0 = Bl[(ks + tig)     * BP + colw];
                uint32_t bl1 = Bl[(ks + tig + 4) * BP + colw];
#pragma unroll
                for (int mt = 0; mt < 2; mt++) {
                    mma_tf32(c[mt * 4 + j], ah[mt], bl0, bl1);   // a_hi * b_lo
                    mma_tf32(c[mt * 4 + j], al[mt], bh0, bh1);   // a_lo * b_hi
                    mma_tf32(c[mt * 4 + j], ah[mt], bh0, bh1);   // a_hi * b_hi
                }
            }
        }
        __syncthreads();
    }

    // epilogue: c[mt*4+j]: {0,1}->row g, {2,3}->row g+8; cols 2*tig
#pragma unroll
    for (int mt = 0; mt < 2; mt++) {
#pragma unroll
        for (int j = 0; j < 4; j++) {
            int col = wn * 32 + j * 8 + tig * 2;
            int r0 = row0 + wmh * 32 + mt * 16 + g;
            float* cc = c[mt * 4 + j];
            if (r0 < N)
                *(float2*)&dst[(size_t)r0 * 128 + col] = make_float2(cc[0], cc[1]);
            int r1 = r0 + 8;
            if (r1 < N)
                *(float2*)&dst[(size_t)r1 * 128 + col] = make_float2(cc[2], cc[3]);
        }
    }
}

// ---------------------------------------------------------------------------
// scan1: per-1024-chunk block scan; local exclusive prefix + chunk total.
__global__ void __launch_bounds__(1024) scan1_kernel(int N) {
    __shared__ int wsum[32];
    int base = blockIdx.x * 1024;
    int t = threadIdx.x, lane = t & 31, w = t >> 5;
    int v = (base + t < N) ? g_cnt[base + t] : 0;

    int x = v;
#pragma unroll
    for (int off = 1; off < 32; off <<= 1) {
        int y = __shfl_up_sync(0xFFFFFFFFu, x, off);
        if (lane >= off) x += y;
    }
    if (lane == 31) wsum[w] = x;
    __syncthreads();
    if (w == 0) {
        int s = wsum[lane];
#pragma unroll
        for (int off = 1; off < 32; off <<= 1) {
            int y = __shfl_up_sync(0xFFFFFFFFu, s, off);
            if (lane >= off) s += y;
        }
        wsum[lane] = s;
    }
    __syncthreads();

    int excl = x - v + (w > 0 ? wsum[w - 1] : 0);
    if (base + t < N) g_rowptr[base + t] = excl;
    if (t == 1023) g_bsum[blockIdx.x] = excl + v;
}

// scan2: exclusive scan of up to 64 chunk totals.
__global__ void __launch_bounds__(64) scan2_kernel(int nb) {
    __shared__ int s[64];
    int t = threadIdx.x;
    int v = (t < nb) ? g_bsum[t] : 0;
    s[t] = v;
    __syncthreads();
#pragma unroll
    for (int off = 1; off < 64; off <<= 1) {
        int add = (t >= off) ? s[t - off] : 0;
        __syncthreads();
        s[t] += add;
        __syncthreads();
    }
    if (t < nb) g_boff[t] = s[t] - v;
}

// scan3: add chunk offsets; materialize rowptr + cursor.
__global__ void __launch_bounds__(1024) scan3_kernel(int N, int E) {
    int i = blockIdx.x * 1024 + threadIdx.x;
    if (i < N) {
        int r = g_rowptr[i] + g_boff[blockIdx.x];
        g_rowptr[i] = r;
        g_cursor[i] = r;
    }
    if (i == 0) g_rowptr[N] = E;
}

// ---------------------------------------------------------------------------
__global__ void fill_kernel(const int* __restrict__ ei, int E, int N) {
    int i = blockIdx.x * blockDim.x + threadIdx.x;
    int stride = gridDim.x * blockDim.x;
    for (int e = i; e < E; e += stride) {
        int d = clampi(ei[E + e], 0, N - 1);
        int pos = atomicAdd(&g_cursor[d], 1);
        g_csrc[pos] = clampi(ei[e], 0, N - 1);
    }
}

// ---------------------------------------------------------------------------
// Aggregate: one BLOCK (128 thr = 4 warps) per dst node. Warp h owns head h;
// thread j = h*32+c owns channel c. Softmax without max-shift (logits O(1);
// shift cancels exactly in alpha). Fused bias+relu+atomicMax pooling.
// ---------------------------------------------------------------------------
__device__ __forceinline__ float warp_sum(float v) {
    v += __shfl_xor_sync(0xFFFFFFFFu, v, 16);
    v += __shfl_xor_sync(0xFFFFFFFFu, v, 8);
    v += __shfl_xor_sync(0xFFFFFFFFu, v, 4);
    v += __shfl_xor_sync(0xFFFFFFFFu, v, 2);
    v += __shfl_xor_sync(0xFFFFFFFFu, v, 1);
    return v;
}

__global__ void __launch_bounds__(128) aggregate_kernel(
    const float* __restrict__ att,
    const float* __restrict__ bias,
    const int* __restrict__ batch,
    int N)
{
    int d = blockIdx.x;
    if (d >= N) return;
    int j = threadIdx.x;

    float xr_v  = g_xr[(size_t)d * 128 + j];
    float att_v = att[j];

    // self loop
    float xs = g_xl[(size_t)d * 128 + j];
    float v  = xs + xr_v;
    v = v > 0.f ? v : 0.2f * v;
    float logit = warp_sum(v * att_v);
    float ex    = __expf(logit);
    float denom = ex;
    float acc   = ex * xs;

    int p    = g_rowptr[d];
    int pend = g_rowptr[d + 1];

    for (; p + 1 < pend; p += 2) {
        int s0 = g_csrc[p], s1 = g_csrc[p + 1];
        float x0 = g_xl[(size_t)s0 * 128 + j];
        float x1 = g_xl[(size_t)s1 * 128 + j];
        float v0 = x0 + xr_v; v0 = v0 > 0.f ? v0 : 0.2f * v0;
        float v1 = x1 + xr_v; v1 = v1 > 0.f ? v1 : 0.2f * v1;
        float t0 = v0 * att_v, t1 = v1 * att_v;
#pragma unroll
        for (int m = 16; m >= 1; m >>= 1) {
            t0 += __shfl_xor_sync(0xFFFFFFFFu, t0, m);
            t1 += __shfl_xor_sync(0xFFFFFFFFu, t1, m);
        }
        float e0 = __expf(t0), e1 = __expf(t1);
        denom += e0 + e1;
        acc   += e0 * x0 + e1 * x1;
    }
    if (p < pend) {
        int s0 = g_csrc[p];
        float x0 = g_xl[(size_t)s0 * 128 + j];
        float v0 = x0 + xr_v; v0 = v0 > 0.f ? v0 : 0.2f * v0;
        float t0 = warp_sum(v0 * att_v);
        float e0 = __expf(t0);
        denom += e0;
        acc   += e0 * x0;
    }

    float o = fmaxf(acc / denom + bias[j], 0.f);
    int g = clampi(batch[d], 0, GMAX - 1);
    atomicMax((int*)&g_pooled[g * 128 + j], __float_as_int(o));
}

// ---------------------------------------------------------------------------
__global__ void __launch_bounds__(128) mlp_kernel(
    const float* __restrict__ W,
    const float* __restrict__ b,
    float* __restrict__ out)
{
    __shared__ float pbuf[128];
    int j = threadIdx.x, g = blockIdx.x;
    pbuf[j] = g_pooled[g * 128 + j];
    __syncthreads();
    float acc = b[j];
#pragma unroll 8
    for (int k = 0; k < 128; k++)
        acc += pbuf[k] * W[k * 128 + j];
    out[g * 128 + j] = fmaxf(acc, 0.f);
}

// ---------------------------------------------------------------------------
extern "C" void kernel_launch(void* const* d_in, const int* in_sizes, int n_in,
                              void* d_out, int out_size)
{
    const float* x     = (const float*)d_in[0];
    const int*   ei    = (const int*)d_in[1];
    const int*   batch = (const int*)d_in[2];
    int base = (n_in >= 10) ? 4 : 3;
    const float* Wl   = (const float*)d_in[base + 0];
    const float* Wr   = (const float*)d_in[base + 1];
    const float* att  = (const float*)d_in[base + 2];
    const float* bias = (const float*)d_in[base + 3];
    const float* Wm   = (const float*)d_in[base + 4];
    const float* bm   = (const float*)d_in[base + 5];

    int N = in_sizes[0] / 128;
    int E = in_sizes[1] / 2;
    int G = out_size / 128;
    float* out = (float*)d_out;
    int nb = (N + 1023) / 1024;

    init_kernel<<<(N + 255) / 256, 256>>>(N, G * 128);                 // 0
    presplit_kernel<<<128, 256>>>(Wl, Wr);                             // 1
    hist_kernel<<<592, 256>>>(ei, E, N);                               // 2

    dim3 ggrid(2, (N + 63) / 64);
    gemm_kernel<<<ggrid, 256>>>(x, N);                                 // 3 (ncu captures idx 3)

    scan1_kernel<<<nb, 1024>>>(N);                                     // 4
    scan2_kernel<<<1, 64>>>(nb);                                       // 5
    scan3_kernel<<<nb, 1024>>>(N, E);                                  // 6
    fill_kernel<<<592, 256>>>(ei, E, N);                               // 7
    aggregate_kernel<<<N, 128>>>(att, bias, batch, N);                 // 8
    mlp_kernel<<<G, 128>>>(Wm, bm, out);                               // 9
}

// round 14
// speedup vs baseline: 1.0833x; 1.0833x over previous
#include <cuda_runtime.h>
#include <cstdint>

// ---------------------------------------------------------------------------
// GATv2 forward, CSR + fused softmax/aggregate/pool.
//   gemm: 3xTF32 mma.sync.m16n8k8 — R12's measured-74.5us structure (A staged
//         in smem pitch 36, warp tile 16x64) with ONE change: B staged by
//         uint4 copy from PRE-SPLIT tf32 hi/lo planes (removes per-block
//         convert: R12 alu=21%). R13's A-from-gmem variant measured WORSE
//         (99.6us: 8-sector scalar LDGs, latency-bound at occ 24%).
//   aggregate: BLOCK per dst node (measured best).
//   CSR build: hist -> 3-step multiblock scan -> fill.
// Shapes: N=50000, E=800000, D=128, H=4, C=32, HC=128, G=64.
// edge_index / batch_ids arrive as int32 (harness canonicalizes int64).
// ---------------------------------------------------------------------------

#define NMAX   50048
#define EMAX   800000
#define GMAX   256
#define AP     36    // A smem pitch: frag bank = 4g + tig (bijective over warp)
#define BP     136   // B smem pitch: frag bank = 8*tig + g (bijective)

__device__ float    g_xl[(size_t)NMAX * 128];
__device__ float    g_xr[(size_t)NMAX * 128];
__device__ uint32_t g_wh[2 * 128 * 128];
__device__ uint32_t g_wlo[2 * 128 * 128];
__device__ int      g_cnt[NMAX];
__device__ int      g_rowptr[NMAX + 1];
__device__ int      g_cursor[NMAX];
__device__ int      g_csrc[EMAX];
__device__ int      g_bsum[64];
__device__ int      g_boff[64];
__device__ float    g_pooled[GMAX * 128];

__device__ __forceinline__ int clampi(int v, int lo, int hi) {
    return v < lo ? lo : (v > hi ? hi : v);
}

__device__ __forceinline__ uint32_t f2tf(float f) {
    uint32_t r;
    asm("cvt.rna.tf32.f32 %0, %1;" : "=r"(r) : "f"(f));
    return r;
}

__device__ __forceinline__ void mma_tf32(float* c, const uint32_t* a,
                                         uint32_t b0, uint32_t b1) {
    asm volatile(
        "mma.sync.aligned.m16n8k8.row.col.f32.tf32.tf32.f32 "
        "{%0,%1,%2,%3}, {%4,%5,%6,%7}, {%8,%9}, {%0,%1,%2,%3};"
        : "+f"(c[0]), "+f"(c[1]), "+f"(c[2]), "+f"(c[3])
        : "r"(a[0]), "r"(a[1]), "r"(a[2]), "r"(a[3]), "r"(b0), "r"(b1));
}

// ---------------------------------------------------------------------------
__global__ void init_kernel(int n_nodes, int n_pool) {
    int i = blockIdx.x * blockDim.x + threadIdx.x;
    int stride = gridDim.x * blockDim.x;
    for (int idx = i; idx < n_nodes; idx += stride) g_cnt[idx] = 0;
    for (int idx = i; idx < n_pool; idx += stride) g_pooled[idx] = 0.f;
}

// ---------------------------------------------------------------------------
// One-time W split: g_wh/g_wlo[cb*16384 + k*128 + col], tf32 hi + residual lo.
// ---------------------------------------------------------------------------
__global__ void presplit_kernel(const float* __restrict__ Wl,
                                const float* __restrict__ Wr) {
    int i = blockIdx.x * 256 + threadIdx.x;
    if (i >= 2 * 16384) return;
    float v = (i < 16384) ? Wl[i] : Wr[i - 16384];
    uint32_t h = f2tf(v);
    g_wh[i]  = h;
    g_wlo[i] = f2tf(v - __uint_as_float(h));
}

// ---------------------------------------------------------------------------
__global__ void hist_kernel(const int* __restrict__ ei, int E, int N) {
    int i = blockIdx.x * blockDim.x + threadIdx.x;
    int stride = gridDim.x * blockDim.x;
    for (int e = i; e < E; e += stride)
        atomicAdd(&g_cnt[clampi(ei[E + e], 0, N - 1)], 1);
}

// ---------------------------------------------------------------------------
// 3xTF32 GEMM (R12 structure + presplit-B copies).
// Block: 64 rows x 128 cols. 8 warps: wm=w&3 (16-row m-tile), wn=w>>2
// (64-col n-half, 8 n-tiles). K in chunks of 32.
// ---------------------------------------------------------------------------
__global__ void __launch_bounds__(256) gemm_kernel(
    const float* __restrict__ x, int N)
{
    __shared__ float    As[64 * AP];   // 9.2 KB
    __shared__ uint32_t Bh[32 * BP];   // 17.4 KB
    __shared__ uint32_t Bl[32 * BP];   // 17.4 KB

    int cb   = blockIdx.x;
    int row0 = blockIdx.y * 64;
    const uint32_t* wh = g_wh  + cb * 16384;
    const uint32_t* wl = g_wlo + cb * 16384;
    float* dst = cb ? g_xr : g_xl;

    int t = threadIdx.x;
    int w = t >> 5, lane = t & 31;
    int wm = w & 3, wn = w >> 2;
    int g = lane >> 2, tig = lane & 3;

    float c[8][4];
#pragma unroll
    for (int j = 0; j < 8; j++)
#pragma unroll
        for (int i = 0; i < 4; i++) c[j][i] = 0.f;

#pragma unroll
    for (int k0 = 0; k0 < 128; k0 += 32) {
        // stage A: 64 rows x 32 cols fp32
#pragma unroll
        for (int i = 0; i < 2; i++) {
            int idx = t + i * 256;            // 0..511 over 64x8 float4
            int r = idx >> 3, c4 = idx & 7;
            float4 v = make_float4(0.f, 0.f, 0.f, 0.f);
            if (row0 + r < N)
                v = *(const float4*)&x[(size_t)(row0 + r) * 128 + k0 + c4 * 4];
            *(float4*)&As[r * AP + c4 * 4] = v;
        }
        // stage B hi/lo: pure uint4 copies from presplit planes
#pragma unroll
        for (int i = 0; i < 4; i++) {
            int idx = t + i * 256;            // 0..1023 over 32k x 32 uint4
            int k = idx >> 5, j4 = idx & 31;
            *(uint4*)&Bh[k * BP + j4 * 4] = *(const uint4*)&wh[(k0 + k) * 128 + j4 * 4];
            *(uint4*)&Bl[k * BP + j4 * 4] = *(const uint4*)&wl[(k0 + k) * 128 + j4 * 4];
        }
        __syncthreads();

#pragma unroll
        for (int ks = 0; ks < 32; ks += 8) {
            // A fragment (m16k8, row-major) + on-the-fly hi/lo split
            float a0f = As[(wm * 16 + g)     * AP + ks + tig];
            float a1f = As[(wm * 16 + g + 8) * AP + ks + tig];
            float a2f = As[(wm * 16 + g)     * AP + ks + tig + 4];
            float a3f = As[(wm * 16 + g + 8) * AP + ks + tig + 4];
            uint32_t ah[4], al[4];
            ah[0] = f2tf(a0f); al[0] = f2tf(a0f - __uint_as_float(ah[0]));
            ah[1] = f2tf(a1f); al[1] = f2tf(a1f - __uint_as_float(ah[1]));
            ah[2] = f2tf(a2f); al[2] = f2tf(a2f - __uint_as_float(ah[2]));
            ah[3] = f2tf(a3f); al[3] = f2tf(a3f - __uint_as_float(ah[3]));

#pragma unroll
            for (int j = 0; j < 8; j++) {
                int col = wn * 64 + j * 8 + g;
                uint32_t bh0 = Bh[(ks + tig)     * BP + col];
                uint32_t bh1 = Bh[(ks + tig + 4) * BP + col];
                uint32_t bl0 = Bl[(ks + tig)     * BP + col];
                uint32_t bl1 = Bl[(ks + tig + 4) * BP + col];
                mma_tf32(c[j], ah, bl0, bl1);   // a_hi * b_lo
                mma_tf32(c[j], al, bh0, bh1);   // a_lo * b_hi
                mma_tf32(c[j], ah, bh0, bh1);   // a_hi * b_hi
            }
        }
        __syncthreads();
    }

    // epilogue: c[j][{0,1}] -> (row, col..col+1), c[j][{2,3}] -> (row+8, ..)
#pragma unroll
    for (int j = 0; j < 8; j++) {
        int col = wn * 64 + j * 8 + tig * 2;
        int r0  = row0 + wm * 16 + g;
        if (r0 < N)
            *(float2*)&dst[(size_t)r0 * 128 + col] = make_float2(c[j][0], c[j][1]);
        int r1 = r0 + 8;
        if (r1 < N)
            *(float2*)&dst[(size_t)r1 * 128 + col] = make_float2(c[j][2], c[j][3]);
    }
}

// ---------------------------------------------------------------------------
// scan1: per-1024-chunk block scan; local exclusive prefix + chunk total.
__global__ void __launch_bounds__(1024) scan1_kernel(int N) {
    __shared__ int wsum[32];
    int base = blockIdx.x * 1024;
    int t = threadIdx.x, lane = t & 31, w = t >> 5;
    int v = (base + t < N) ? g_cnt[base + t] : 0;

    int x = v;
#pragma unroll
    for (int off = 1; off < 32; off <<= 1) {
        int y = __shfl_up_sync(0xFFFFFFFFu, x, off);
        if (lane >= off) x += y;
    }
    if (lane == 31) wsum[w] = x;
    __syncthreads();
    if (w == 0) {
        int s = wsum[lane];
#pragma unroll
        for (int off = 1; off < 32; off <<= 1) {
            int y = __shfl_up_sync(0xFFFFFFFFu, s, off);
            if (lane >= off) s += y;
        }
        wsum[lane] = s;
    }
    __syncthreads();

    int excl = x - v + (w > 0 ? wsum[w - 1] : 0);
    if (base + t < N) g_rowptr[base + t] = excl;
    if (t == 1023) g_bsum[blockIdx.x] = excl + v;
}

// scan2: exclusive scan of up to 64 chunk totals.
__global__ void __launch_bounds__(64) scan2_kernel(int nb) {
    __shared__ int s[64];
    int t = threadIdx.x;
    int v = (t < nb) ? g_bsum[t] : 0;
    s[t] = v;
    __syncthreads();
#pragma unroll
    for (int off = 1; off < 64; off <<= 1) {
        int add = (t >= off) ? s[t - off] : 0;
        __syncthreads();
        s[t] += add;
        __syncthreads();
    }
    if (t < nb) g_boff[t] = s[t] - v;
}

// scan3: add chunk offsets; materialize rowptr + cursor.
__global__ void __launch_bounds__(1024) scan3_kernel(int N, int E) {
    int i = blockIdx.x * 1024 + threadIdx.x;
    if (i < N) {
        int r = g_rowptr[i] + g_boff[blockIdx.x];
        g_rowptr[i] = r;
        g_cursor[i] = r;
    }
    if (i == 0) g_rowptr[N] = E;
}

// ---------------------------------------------------------------------------
__global__ void fill_kernel(const int* __restrict__ ei, int E, int N) {
    int i = blockIdx.x * blockDim.x + threadIdx.x;
    int stride = gridDim.x * blockDim.x;
    for (int e = i; e < E; e += stride) {
        int d = clampi(ei[E + e], 0, N - 1);
        int pos = atomicAdd(&g_cursor[d], 1);
        g_csrc[pos] = clampi(ei[e], 0, N - 1);
    }
}

// ---------------------------------------------------------------------------
// Aggregate: one BLOCK (128 thr = 4 warps) per dst node. Warp h owns head h;
// thread j = h*32+c owns channel c. Softmax without max-shift (logits O(1);
// shift cancels exactly in alpha). Fused bias+relu+atomicMax pooling.
// ---------------------------------------------------------------------------
__device__ __forceinline__ float warp_sum(float v) {
    v += __shfl_xor_sync(0xFFFFFFFFu, v, 16);
    v += __shfl_xor_sync(0xFFFFFFFFu, v, 8);
    v += __shfl_xor_sync(0xFFFFFFFFu, v, 4);
    v += __shfl_xor_sync(0xFFFFFFFFu, v, 2);
    v += __shfl_xor_sync(0xFFFFFFFFu, v, 1);
    return v;
}

__global__ void __launch_bounds__(128) aggregate_kernel(
    const float* __restrict__ att,
    const float* __restrict__ bias,
    const int* __restrict__ batch,
    int N)
{
    int d = blockIdx.x;
    if (d >= N) return;
    int j = threadIdx.x;

    float xr_v  = g_xr[(size_t)d * 128 + j];
    float att_v = att[j];

    // self loop
    float xs = g_xl[(size_t)d * 128 + j];
    float v  = xs + xr_v;
    v = v > 0.f ? v : 0.2f * v;
    float logit = warp_sum(v * att_v);
    float ex    = __expf(logit);
    float denom = ex;
    float acc   = ex * xs;

    int p    = g_rowptr[d];
    int pend = g_rowptr[d + 1];

    for (; p + 1 < pend; p += 2) {
        int s0 = g_csrc[p], s1 = g_csrc[p + 1];
        float x0 = g_xl[(size_t)s0 * 128 + j];
        float x1 = g_xl[(size_t)s1 * 128 + j];
        float v0 = x0 + xr_v; v0 = v0 > 0.f ? v0 : 0.2f * v0;
        float v1 = x1 + xr_v; v1 = v1 > 0.f ? v1 : 0.2f * v1;
        float t0 = v0 * att_v, t1 = v1 * att_v;
#pragma unroll
        for (int m = 16; m >= 1; m >>= 1) {
            t0 += __shfl_xor_sync(0xFFFFFFFFu, t0, m);
            t1 += __shfl_xor_sync(0xFFFFFFFFu, t1, m);
        }
        float e0 = __expf(t0), e1 = __expf(t1);
        denom += e0 + e1;
        acc   += e0 * x0 + e1 * x1;
    }
    if (p < pend) {
        int s0 = g_csrc[p];
        float x0 = g_xl[(size_t)s0 * 128 + j];
        float v0 = x0 + xr_v; v0 = v0 > 0.f ? v0 : 0.2f * v0;
        float t0 = warp_sum(v0 * att_v);
        float e0 = __expf(t0);
        denom += e0;
        acc   += e0 * x0;
    }

    float o = fmaxf(acc / denom + bias[j], 0.f);
    int g = clampi(batch[d], 0, GMAX - 1);
    atomicMax((int*)&g_pooled[g * 128 + j], __float_as_int(o));
}

// ---------------------------------------------------------------------------
__global__ void __launch_bounds__(128) mlp_kernel(
    const float* __restrict__ W,
    const float* __restrict__ b,
    float* __restrict__ out)
{
    __shared__ float pbuf[128];
    int j = threadIdx.x, g = blockIdx.x;
    pbuf[j] = g_pooled[g * 128 + j];
    __syncthreads();
    float acc = b[j];
#pragma unroll 8
    for (int k = 0; k < 128; k++)
        acc += pbuf[k] * W[k * 128 + j];
    out[g * 128 + j] = fmaxf(acc, 0.f);
}

// ---------------------------------------------------------------------------
extern "C" void kernel_launch(void* const* d_in, const int* in_sizes, int n_in,
                              void* d_out, int out_size)
{
    const float* x     = (const float*)d_in[0];
    const int*   ei    = (const int*)d_in[1];
    const int*   batch = (const int*)d_in[2];
    int base = (n_in >= 10) ? 4 : 3;
    const float* Wl   = (const float*)d_in[base + 0];
    const float* Wr   = (const float*)d_in[base + 1];
    const float* att  = (const float*)d_in[base + 2];
    const float* bias = (const float*)d_in[base + 3];
    const float* Wm   = (const float*)d_in[base + 4];
    const float* bm   = (const float*)d_in[base + 5];

    int N = in_sizes[0] / 128;
    int E = in_sizes[1] / 2;
    int G = out_size / 128;
    float* out = (float*)d_out;
    int nb = (N + 1023) / 1024;

    init_kernel<<<(N + 255) / 256, 256>>>(N, G * 128);                 // 0
    presplit_kernel<<<128, 256>>>(Wl, Wr);                             // 1
    hist_kernel<<<592, 256>>>(ei, E, N);                               // 2

    dim3 ggrid(2, (N + 63) / 64);
    gemm_kernel<<<ggrid, 256>>>(x, N);                                 // 3 (ncu captures idx 3)

    scan1_kernel<<<nb, 1024>>>(N);                                     // 4
    scan2_kernel<<<1, 64>>>(nb);                                       // 5
    scan3_kernel<<<nb, 1024>>>(N, E);                                  // 6
    fill_kernel<<<592, 256>>>(ei, E, N);                               // 7
    aggregate_kernel<<<N, 128>>>(att, bias, batch, N);                 // 8
    mlp_kernel<<<G, 128>>>(Wm, bm, out);                               // 9
}

// round 15
// speedup vs baseline: 1.1304x; 1.0435x over previous
#include <cuda_runtime.h>
#include <cstdint>

// ---------------------------------------------------------------------------
// GATv2 forward, CSR + fused softmax/aggregate/pool.
//   gemm: 3xTF32 mma.sync.m16n8k8, DOUBLE-BUFFERED cp.async staging
//         (R12/R14 single-buffer versions serialized stage->compute per
//         chunk: tensor pinned at 46-50%, issue 28%). K-chunk 16 so two
//         A+Bh+Bl buffers fit the 48KB static smem cap. W pre-split once
//         into tf32 hi/lo planes.
//   aggregate: BLOCK per dst node (measured best).
//   CSR build: hist -> 3-step multiblock scan -> fill.
// Shapes: N=50000, E=800000, D=128, H=4, C=32, HC=128, G=64.
// edge_index / batch_ids arrive as int32 (harness canonicalizes int64).
// ---------------------------------------------------------------------------

#define NMAX   50048
#define EMAX   800000
#define GMAX   256
#define AP     20    // A smem pitch (chunk 16): frag banks (20g+tig)%32 bijective
#define BP     136   // B smem pitch: frag bank = 8*tig + g (bijective)

__device__ float    g_xl[(size_t)NMAX * 128];
__device__ float    g_xr[(size_t)NMAX * 128];
__device__ uint32_t g_wh[2 * 128 * 128];
__device__ uint32_t g_wlo[2 * 128 * 128];
__device__ int      g_cnt[NMAX];
__device__ int      g_rowptr[NMAX + 1];
__device__ int      g_cursor[NMAX];
__device__ int      g_csrc[EMAX];
__device__ int      g_bsum[64];
__device__ int      g_boff[64];
__device__ float    g_pooled[GMAX * 128];

__device__ __forceinline__ int clampi(int v, int lo, int hi) {
    return v < lo ? lo : (v > hi ? hi : v);
}

__device__ __forceinline__ uint32_t f2tf(float f) {
    uint32_t r;
    asm("cvt.rna.tf32.f32 %0, %1;" : "=r"(r) : "f"(f));
    return r;
}

__device__ __forceinline__ void mma_tf32(float* c, const uint32_t* a,
                                         uint32_t b0, uint32_t b1) {
    asm volatile(
        "mma.sync.aligned.m16n8k8.row.col.f32.tf32.tf32.f32 "
        "{%0,%1,%2,%3}, {%4,%5,%6,%7}, {%8,%9}, {%0,%1,%2,%3};"
        : "+f"(c[0]), "+f"(c[1]), "+f"(c[2]), "+f"(c[3])
        : "r"(a[0]), "r"(a[1]), "r"(a[2]), "r"(a[3]), "r"(b0), "r"(b1));
}

__device__ __forceinline__ void cp16(uint32_t smem_dst, const void* gmem_src, int src_bytes) {
    asm volatile("cp.async.cg.shared.global [%0], [%1], 16, %2;"
                 :: "r"(smem_dst), "l"(gmem_src), "r"(src_bytes));
}
__device__ __forceinline__ void cp_commit() {
    asm volatile("cp.async.commit_group;");
}
__device__ __forceinline__ void cp_wait1() {
    asm volatile("cp.async.wait_group 1;");
}

// ---------------------------------------------------------------------------
__global__ void init_kernel(int n_nodes, int n_pool) {
    int i = blockIdx.x * blockDim.x + threadIdx.x;
    int stride = gridDim.x * blockDim.x;
    for (int idx = i; idx < n_nodes; idx += stride) g_cnt[idx] = 0;
    for (int idx = i; idx < n_pool; idx += stride) g_pooled[idx] = 0.f;
}

// ---------------------------------------------------------------------------
// One-time W split: g_wh/g_wlo[cb*16384 + k*128 + col], tf32 hi + residual lo.
// ---------------------------------------------------------------------------
__global__ void presplit_kernel(const float* __restrict__ Wl,
                                const float* __restrict__ Wr) {
    int i = blockIdx.x * 256 + threadIdx.x;
    if (i >= 2 * 16384) return;
    float v = (i < 16384) ? Wl[i] : Wr[i - 16384];
    uint32_t h = f2tf(v);
    g_wh[i]  = h;
    g_wlo[i] = f2tf(v - __uint_as_float(h));
}

// ---------------------------------------------------------------------------
__global__ void hist_kernel(const int* __restrict__ ei, int E, int N) {
    int i = blockIdx.x * blockDim.x + threadIdx.x;
    int stride = gridDim.x * blockDim.x;
    for (int e = i; e < E; e += stride)
        atomicAdd(&g_cnt[clampi(ei[E + e], 0, N - 1)], 1);
}

// ---------------------------------------------------------------------------
// 3xTF32 GEMM, double-buffered cp.async, K in 8 chunks of 16.
// Block: 64 rows x 128 cols. 8 warps: wm=w&3 (16-row m-tile), wn=w>>2
// (64-col n-half, 8 n-tiles).
// ---------------------------------------------------------------------------
__global__ void __launch_bounds__(256) gemm_kernel(
    const float* __restrict__ x, int N)
{
    __shared__ float    As[2][64 * AP];    // 10.2 KB
    __shared__ uint32_t Bh[2][16 * BP];    // 17.4 KB
    __shared__ uint32_t Bl[2][16 * BP];    // 17.4 KB

    int cb   = blockIdx.x;
    int row0 = blockIdx.y * 64;
    const uint32_t* wh = g_wh  + cb * 16384;
    const uint32_t* wl = g_wlo + cb * 16384;
    float* dst = cb ? g_xr : g_xl;

    int t = threadIdx.x;
    int w = t >> 5, lane = t & 31;
    int wm = w & 3, wn = w >> 2;
    int g = lane >> 2, tig = lane & 3;

    // staging coordinates (fixed per thread)
    int ar  = t >> 2;              // A row 0..63 (1 float4/thread/chunk)
    int ac4 = t & 3;               // A col-quad 0..3
    const float* a_src_base = &x[(size_t)clampi(row0 + ar, 0, N - 1) * 128 + ac4 * 4];
    int a_bytes = (row0 + ar < N) ? 16 : 0;
    uint32_t a_dst = (uint32_t)__cvta_generic_to_shared(&As[0][ar * AP + ac4 * 4]);
    uint32_t a_buf_stride = (uint32_t)((char*)&As[1][0] - (char*)&As[0][0]);

    uint32_t b_dst[4];
    const uint32_t* b_src[4];
#pragma unroll
    for (int i = 0; i < 4; i++) {
        int idx = t + i * 256;             // 0..1023
        int plane = idx >> 9;              // 0=hi, 1=lo
        int rem = idx & 511;
        int k = rem >> 5, j4 = rem & 31;
        b_dst[i] = (uint32_t)__cvta_generic_to_shared(
            plane ? &Bl[0][k * BP + j4 * 4] : &Bh[0][k * BP + j4 * 4]);
        b_src[i] = (plane ? wl : wh) + k * 128 + j4 * 4;
    }
    uint32_t b_buf_stride = (uint32_t)((char*)&Bh[1][0] - (char*)&Bh[0][0]);

    float c[8][4];
#pragma unroll
    for (int j = 0; j < 8; j++)
#pragma unroll
        for (int i = 0; i < 4; i++) c[j][i] = 0.f;

    // stage chunk 0
    cp16(a_dst, a_src_base, a_bytes);
#pragma unroll
    for (int i = 0; i < 4; i++) cp16(b_dst[i], b_src[i], 16);
    cp_commit();

#pragma unroll
    for (int ch = 0; ch < 8; ch++) {
        int buf = ch & 1;
        // prefetch chunk ch+1 into the other buffer
        if (ch < 7) {
            int nbuf = (ch + 1) & 1;
            int koff = (ch + 1) * 16;
            cp16(a_dst + nbuf * a_buf_stride, a_src_base + koff, a_bytes);
#pragma unroll
            for (int i = 0; i < 4; i++)
                cp16(b_dst[i] + nbuf * b_buf_stride, b_src[i] + koff * 128, 16);
        }
        cp_commit();
        cp_wait1();            // chunk ch resident
        __syncthreads();

        const float*    as = As[buf];
        const uint32_t* bh = Bh[buf];
        const uint32_t* bl = Bl[buf];

#pragma unroll
        for (int ks = 0; ks < 16; ks += 8) {
            float a0f = as[(wm * 16 + g)     * AP + ks + tig];
            float a1f = as[(wm * 16 + g + 8) * AP + ks + tig];
            float a2f = as[(wm * 16 + g)     * AP + ks + tig + 4];
            float a3f = as[(wm * 16 + g + 8) * AP + ks + tig + 4];
            uint32_t ah[4], al[4];
            ah[0] = f2tf(a0f); al[0] = f2tf(a0f - __uint_as_float(ah[0]));
            ah[1] = f2tf(a1f); al[1] = f2tf(a1f - __uint_as_float(ah[1]));
            ah[2] = f2tf(a2f); al[2] = f2tf(a2f - __uint_as_float(ah[2]));
            ah[3] = f2tf(a3f); al[3] = f2tf(a3f - __uint_as_float(ah[3]));

#pragma unroll
            for (int j = 0; j < 8; j++) {
                int col = wn * 64 + j * 8 + g;
                uint32_t bh0 = bh[(ks + tig)     * BP + col];
                uint32_t bh1 = bh[(ks + tig + 4) * BP + col];
                uint32_t bl0 = bl[(ks + tig)     * BP + col];
                uint32_t bl1 = bl[(ks + tig + 4) * BP + col];
                mma_tf32(c[j], ah, bl0, bl1);   // a_hi * b_lo
                mma_tf32(c[j], al, bh0, bh1);   // a_lo * b_hi
                mma_tf32(c[j], ah, bh0, bh1);   // a_hi * b_hi
            }
        }
        __syncthreads();       // buffer safe to overwrite next iteration
    }

    // epilogue: c[j][{0,1}] -> (row, col..col+1), c[j][{2,3}] -> (row+8, ..)
#pragma unroll
    for (int j = 0; j < 8; j++) {
        int col = wn * 64 + j * 8 + tig * 2;
        int r0  = row0 + wm * 16 + g;
        if (r0 < N)
            *(float2*)&dst[(size_t)r0 * 128 + col] = make_float2(c[j][0], c[j][1]);
        int r1 = r0 + 8;
        if (r1 < N)
            *(float2*)&dst[(size_t)r1 * 128 + col] = make_float2(c[j][2], c[j][3]);
    }
}

// ---------------------------------------------------------------------------
// scan1: per-1024-chunk block scan; local exclusive prefix + chunk total.
__global__ void __launch_bounds__(1024) scan1_kernel(int N) {
    __shared__ int wsum[32];
    int base = blockIdx.x * 1024;
    int t = threadIdx.x, lane = t & 31, w = t >> 5;
    int v = (base + t < N) ? g_cnt[base + t] : 0;

    int x = v;
#pragma unroll
    for (int off = 1; off < 32; off <<= 1) {
        int y = __shfl_up_sync(0xFFFFFFFFu, x, off);
        if (lane >= off) x += y;
    }
    if (lane == 31) wsum[w] = x;
    __syncthreads();
    if (w == 0) {
        int s = wsum[lane];
#pragma unroll
        for (int off = 1; off < 32; off <<= 1) {
            int y = __shfl_up_sync(0xFFFFFFFFu, s, off);
            if (lane >= off) s += y;
        }
        wsum[lane] = s;
    }
    __syncthreads();

    int excl = x - v + (w > 0 ? wsum[w - 1] : 0);
    if (base + t < N) g_rowptr[base + t] = excl;
    if (t == 1023) g_bsum[blockIdx.x] = excl + v;
}

// scan2: exclusive scan of up to 64 chunk totals.
__global__ void __launch_bounds__(64) scan2_kernel(int nb) {
    __shared__ int s[64];
    int t = threadIdx.x;
    int v = (t < nb) ? g_bsum[t] : 0;
    s[t] = v;
    __syncthreads();
#pragma unroll
    for (int off = 1; off < 64; off <<= 1) {
        int add = (t >= off) ? s[t - off] : 0;
        __syncthreads();
        s[t] += add;
        __syncthreads();
    }
    if (t < nb) g_boff[t] = s[t] - v;
}

// scan3: add chunk offsets; materialize rowptr + cursor.
__global__ void __launch_bounds__(1024) scan3_kernel(int N, int E) {
    int i = blockIdx.x * 1024 + threadIdx.x;
    if (i < N) {
        int r = g_rowptr[i] + g_boff[blockIdx.x];
        g_rowptr[i] = r;
        g_cursor[i] = r;
    }
    if (i == 0) g_rowptr[N] = E;
}

// ---------------------------------------------------------------------------
__global__ void fill_kernel(const int* __restrict__ ei, int E, int N) {
    int i = blockIdx.x * blockDim.x + threadIdx.x;
    int stride = gridDim.x * blockDim.x;
    for (int e = i; e < E; e += stride) {
        int d = clampi(ei[E + e], 0, N - 1);
        int pos = atomicAdd(&g_cursor[d], 1);
        g_csrc[pos] = clampi(ei[e], 0, N - 1);
    }
}

// ---------------------------------------------------------------------------
// Aggregate: one BLOCK (128 thr = 4 warps) per dst node. Warp h owns head h;
// thread j = h*32+c owns channel c. Softmax without max-shift (logits O(1);
// shift cancels exactly in alpha). Fused bias+relu+atomicMax pooling.
// ---------------------------------------------------------------------------
__device__ __forceinline__ float warp_sum(float v) {
    v += __shfl_xor_sync(0xFFFFFFFFu, v, 16);
    v += __shfl_xor_sync(0xFFFFFFFFu, v, 8);
    v += __shfl_xor_sync(0xFFFFFFFFu, v, 4);
    v += __shfl_xor_sync(0xFFFFFFFFu, v, 2);
    v += __shfl_xor_sync(0xFFFFFFFFu, v, 1);
    return v;
}

__global__ void __launch_bounds__(128) aggregate_kernel(
    const float* __restrict__ att,
    const float* __restrict__ bias,
    const int* __restrict__ batch,
    int N)
{
    int d = blockIdx.x;
    if (d >= N) return;
    int j = threadIdx.x;

    float xr_v  = g_xr[(size_t)d * 128 + j];
    float att_v = att[j];

    // self loop
    float xs = g_xl[(size_t)d * 128 + j];
    float v  = xs + xr_v;
    v = v > 0.f ? v : 0.2f * v;
    float logit = warp_sum(v * att_v);
    float ex    = __expf(logit);
    float denom = ex;
    float acc   = ex * xs;

    int p    = g_rowptr[d];
    int pend = g_rowptr[d + 1];

    for (; p + 1 < pend; p += 2) {
        int s0 = g_csrc[p], s1 = g_csrc[p + 1];
        float x0 = g_xl[(size_t)s0 * 128 + j];
        float x1 = g_xl[(size_t)s1 * 128 + j];
        float v0 = x0 + xr_v; v0 = v0 > 0.f ? v0 : 0.2f * v0;
        float v1 = x1 + xr_v; v1 = v1 > 0.f ? v1 : 0.2f * v1;
        float t0 = v0 * att_v, t1 = v1 * att_v;
#pragma unroll
        for (int m = 16; m >= 1; m >>= 1) {
            t0 += __shfl_xor_sync(0xFFFFFFFFu, t0, m);
            t1 += __shfl_xor_sync(0xFFFFFFFFu, t1, m);
        }
        float e0 = __expf(t0), e1 = __expf(t1);
        denom += e0 + e1;
        acc   += e0 * x0 + e1 * x1;
    }
    if (p < pend) {
        int s0 = g_csrc[p];
        float x0 = g_xl[(size_t)s0 * 128 + j];
        float v0 = x0 + xr_v; v0 = v0 > 0.f ? v0 : 0.2f * v0;
        float t0 = warp_sum(v0 * att_v);
        float e0 = __expf(t0);
        denom += e0;
        acc   += e0 * x0;
    }

    float o = fmaxf(acc / denom + bias[j], 0.f);
    int g = clampi(batch[d], 0, GMAX - 1);
    atomicMax((int*)&g_pooled[g * 128 + j], __float_as_int(o));
}

// ---------------------------------------------------------------------------
__global__ void __launch_bounds__(128) mlp_kernel(
    const float* __restrict__ W,
    const float* __restrict__ b,
    float* __restrict__ out)
{
    __shared__ float pbuf[128];
    int j = threadIdx.x, g = blockIdx.x;
    pbuf[j] = g_pooled[g * 128 + j];
    __syncthreads();
    float acc = b[j];
#pragma unroll 8
    for (int k = 0; k < 128; k++)
        acc += pbuf[k] * W[k * 128 + j];
    out[g * 128 + j] = fmaxf(acc, 0.f);
}

// ---------------------------------------------------------------------------
extern "C" void kernel_launch(void* const* d_in, const int* in_sizes, int n_in,
                              void* d_out, int out_size)
{
    const float* x     = (const float*)d_in[0];
    const int*   ei    = (const int*)d_in[1];
    const int*   batch = (const int*)d_in[2];
    int base = (n_in >= 10) ? 4 : 3;
    const float* Wl   = (const float*)d_in[base + 0];
    const float* Wr   = (const float*)d_in[base + 1];
    const float* att  = (const float*)d_in[base + 2];
    const float* bias = (const float*)d_in[base + 3];
    const float* Wm   = (const float*)d_in[base + 4];
    const float* bm   = (const float*)d_in[base + 5];

    int N = in_sizes[0] / 128;
    int E = in_sizes[1] / 2;
    int G = out_size / 128;
    float* out = (float*)d_out;
    int nb = (N + 1023) / 1024;

    init_kernel<<<(N + 255) / 256, 256>>>(N, G * 128);                 // 0
    presplit_kernel<<<128, 256>>>(Wl, Wr);                             // 1
    hist_kernel<<<592, 256>>>(ei, E, N);                               // 2

    dim3 ggrid(2, (N + 63) / 64);
    gemm_kernel<<<ggrid, 256>>>(x, N);                                 // 3 (ncu captures idx 3)

    scan1_kernel<<<nb, 1024>>>(N);                                     // 4
    scan2_kernel<<<1, 64>>>(nb);                                       // 5
    scan3_kernel<<<nb, 1024>>>(N, E);                                  // 6
    fill_kernel<<<592, 256>>>(ei, E, N);                               // 7
    aggregate_kernel<<<N, 128>>>(att, bias, batch, N);                 // 8
    mlp_kernel<<<G, 128>>>(Wm, bm, out);                               // 9
}